// round 12
// baseline (speedup 1.0000x reference)
#include <cuda_runtime.h>

// ContrastHead: neighbor-contrastive loss.
//   N=200000 points, K=16 neighbors, C=32 features, T=0.1, weight=0.1, eps=1e-8
// Inputs: features f32 [N*C], labels i32 [N], neighbor_idx [N*K] (int32/int64 detect)
// Output: 1 float.
//
// R12: single fused kernel. Best-measured main body (R10/R11: f32 quarter-warp
// gather, in-kernel dtype detect, per-block double atomics) + last-block-done
// finalize (ticket counter; last block writes out and resets accumulators for the
// next graph replay). Removes the 4.2us second-launch tail.

#define KNB 16
#define CF  32

__device__ double g_num = 0.0;        // reset by the last block every call
__device__ double g_den = 0.0;
__device__ unsigned g_ticket = 0;

__global__ __launch_bounds__(256) void ch_fused_kernel(
    const float* __restrict__ feat,
    const int*   __restrict__ labels,
    const void*  __restrict__ nbr,
    float* __restrict__ out,
    int n)
{
    const unsigned FULL = 0xffffffffu;
    const int lane = threadIdx.x & 31;
    const int wid  = threadIdx.x >> 5;
    const int wp   = (blockIdx.x * blockDim.x + threadIdx.x) >> 5;   // warp -> point
    const bool active = (wp < n);
    const int p = active ? wp : 0;

    // dtype detect: int64 -> odd 32-bit words of first 16 entries all zero.
    int probe = 1;
    if (lane < 16) probe = reinterpret_cast<const int*>(nbr)[2 * lane + 1];
    const bool is64 = ((__ballot_sync(FULL, probe == 0) & 0xFFFFu) == 0xFFFFu);

    // center label (uniform broadcast load)
    const int lab = labels[p];

    // Quarter-warp layout: sublane s in [0,8) holds float4 chunk s of any row.
    const int s = lane & 7;
    const float4 cf = reinterpret_cast<const float4*>(feat + (size_t)p * CF)[s];

    // lanes 0..15: this lane's neighbor index and neighbor label
    int myidx = 0;
    if (lane < KNB) {
        if (is64)
            myidx = (int)reinterpret_cast<const long long*>(nbr)[(size_t)p * KNB + lane];
        else
            myidx = reinterpret_cast<const int*>(nbr)[(size_t)p * KNB + lane];
    }
    const int nblab = labels[(lane < KNB) ? myidx : 0];

    // Distances: iteration t handles neighbors t*4 .. t*4+3, one per 8-lane quarter.
    float dist2 = 0.0f;
#pragma unroll
    for (int t = 0; t < 4; t++) {
        const int j_src = t * 4 + (lane >> 3);
        const int idx = __shfl_sync(FULL, myidx, j_src);
        const float4 nf = reinterpret_cast<const float4*>(feat + (size_t)idx * CF)[s];
        const float d0 = cf.x - nf.x, d1 = cf.y - nf.y;
        const float d2 = cf.z - nf.z, d3 = cf.w - nf.w;
        float sum = d0 * d0;
        sum = fmaf(d1, d1, sum);
        sum = fmaf(d2, d2, sum);
        sum = fmaf(d3, d3, sum);
        sum += __shfl_xor_sync(FULL, sum, 4);
        sum += __shfl_xor_sync(FULL, sum, 2);
        sum += __shfl_xor_sync(FULL, sum, 1);
        // quarter q's total lives at lane q*8; route to owner lane t*4+q
        const float cand = __shfl_sync(FULL, sum, (lane & 3) << 3);
        if ((lane >> 2) == t) dist2 = cand;
    }

    // lanes 0..15 now hold dist^2 for neighbor `lane`
    const float nd = (lane < KNB) ? -sqrtf(dist2 + 1e-8f) : -1e30f;

    // stable softmax: max over the 16 neighbor lanes (xor<16 never crosses halves)
    float m = nd;
    m = fmaxf(m, __shfl_xor_sync(FULL, m, 8));
    m = fmaxf(m, __shfl_xor_sync(FULL, m, 4));
    m = fmaxf(m, __shfl_xor_sync(FULL, m, 2));
    m = fmaxf(m, __shfl_xor_sync(FULL, m, 1));

    const float e = (lane < KNB) ? __expf((nd - m) * 10.0f) : 0.0f;   // 1/T = 10
    const bool ispos = (lane < KNB) && (nblab == lab);
    float pos = ispos ? e : 0.0f;
    float neg = e;
#pragma unroll
    for (int off = 8; off >= 1; off >>= 1) {
        pos += __shfl_xor_sync(FULL, pos, off);
        neg += __shfl_xor_sync(FULL, neg, off);
    }
    const int cnt = __popc(__ballot_sync(FULL, ispos) & 0xFFFFu);

    __shared__ float sn[8], sd[8];
    if (lane == 0) {
        const float pm = (active && cnt > 0 && cnt < KNB) ? 1.0f : 0.0f;
        const float loss = -__logf(pos / neg + 1e-8f);
        sn[wid] = loss * pm;
        sd[wid] = pm;
    }
    __syncthreads();
    if (threadIdx.x == 0) {
        float a = 0.0f, b = 0.0f;
#pragma unroll
        for (int i = 0; i < 8; i++) { a += sn[i]; b += sd[i]; }
        atomicAdd(&g_num, (double)a);
        atomicAdd(&g_den, (double)b);

        // last-block-done finalize
        __threadfence();
        const unsigned ticket = atomicAdd(&g_ticket, 1u);
        if (ticket == gridDim.x - 1) {
            double den = g_den;
            if (den < 1.0) den = 1.0;
            out[0] = (float)(g_num / den * 0.1);   // WEIGHT = 0.1
            // reset for the next graph replay (deterministic per call)
            g_num = 0.0;
            g_den = 0.0;
            g_ticket = 0;
        }
    }
}

extern "C" void kernel_launch(void* const* d_in, const int* in_sizes, int n_in,
                              void* d_out, int out_size) {
    const float* feat   = (const float*)d_in[0];
    const int*   labels = (const int*)d_in[1];
    const void*  nbr    = (const void*)d_in[2];
    float* out = (float*)d_out;
    (void)n_in; (void)out_size;

    const int n = in_sizes[1];        // N points
    const int blocks = (n + 7) / 8;   // warp per point, 8 warps/block

    ch_fused_kernel<<<blocks, 256>>>(feat, labels, nbr, out, n);
}

// round 13
// speedup vs baseline: 1.1293x; 1.1293x over previous
#include <cuda_runtime.h>

// ContrastHead: neighbor-contrastive loss.
//   N=200000 points, K=16 neighbors, C=32 features, T=0.1, weight=0.1, eps=1e-8
// Inputs: features f32 [N*C], labels i32 [N], neighbor_idx [N*K] (int32/int64 detect)
// Output: 1 float.
//
// R13: R11 split structure (best: 58.1us) with the gather loop restructured for
// MLP=4 — all 4 index shuffles, then 4 independent LDG.128s, then 4 parallel
// butterfly reductions. Profile showed main at ~80% issue AND ~80% L1tex with ~40%
// stall-idle slots; batching overlaps gather latency to close the issue gap.

#define KNB 16
#define CF  32

__device__ double g_num = 0.0;   // finalize re-zeroes after each read
__device__ double g_den = 0.0;

__global__ __launch_bounds__(256) void ch_main_kernel(
    const float* __restrict__ feat,
    const int*   __restrict__ labels,
    const void*  __restrict__ nbr,
    int n)
{
    const unsigned FULL = 0xffffffffu;
    const int lane = threadIdx.x & 31;
    const int wid  = threadIdx.x >> 5;
    const int wp   = (blockIdx.x * blockDim.x + threadIdx.x) >> 5;   // warp -> point
    const bool active = (wp < n);
    const int p = active ? wp : 0;
    const int s = lane & 7;    // float4 chunk within 128B row
    const int q = lane >> 3;   // quarter id 0..3

    // dtype detect: int64 -> odd 32-bit words of first 16 entries all zero.
    int probe = 1;
    if (lane < 16) probe = reinterpret_cast<const int*>(nbr)[2 * lane + 1];
    const bool is64 = ((__ballot_sync(FULL, probe == 0) & 0xFFFFu) == 0xFFFFu);

    const float4* __restrict__ feat4 = reinterpret_cast<const float4*>(feat);

    // issue idx + center loads up front
    int myidx = 0;
    if (lane < KNB) {
        if (is64)
            myidx = (int)reinterpret_cast<const long long*>(nbr)[(size_t)p * KNB + lane];
        else
            myidx = reinterpret_cast<const int*>(nbr)[(size_t)p * KNB + lane];
    }
    const float4 cf = feat4[(size_t)p * 8 + s];
    const int lab = labels[p];

    // batched gathers: quarter q handles neighbors t*4+q for t=0..3
    const int i0 = __shfl_sync(FULL, myidx,      q);
    const int i1 = __shfl_sync(FULL, myidx,  4 + q);
    const int i2 = __shfl_sync(FULL, myidx,  8 + q);
    const int i3 = __shfl_sync(FULL, myidx, 12 + q);
    const float4 nf0 = feat4[(size_t)i0 * 8 + s];
    const float4 nf1 = feat4[(size_t)i1 * 8 + s];
    const float4 nf2 = feat4[(size_t)i2 * 8 + s];
    const float4 nf3 = feat4[(size_t)i3 * 8 + s];
    const int nblab = labels[(lane < KNB) ? myidx : 0];

    float s0, s1, s2, s3;
    {
        float d0, d1, d2, d3;
        d0 = cf.x - nf0.x; d1 = cf.y - nf0.y; d2 = cf.z - nf0.z; d3 = cf.w - nf0.w;
        s0 = fmaf(d3, d3, fmaf(d2, d2, fmaf(d1, d1, d0 * d0)));
        d0 = cf.x - nf1.x; d1 = cf.y - nf1.y; d2 = cf.z - nf1.z; d3 = cf.w - nf1.w;
        s1 = fmaf(d3, d3, fmaf(d2, d2, fmaf(d1, d1, d0 * d0)));
        d0 = cf.x - nf2.x; d1 = cf.y - nf2.y; d2 = cf.z - nf2.z; d3 = cf.w - nf2.w;
        s2 = fmaf(d3, d3, fmaf(d2, d2, fmaf(d1, d1, d0 * d0)));
        d0 = cf.x - nf3.x; d1 = cf.y - nf3.y; d2 = cf.z - nf3.z; d3 = cf.w - nf3.w;
        s3 = fmaf(d3, d3, fmaf(d2, d2, fmaf(d1, d1, d0 * d0)));
    }
    // 4 independent butterfly chains within each 8-lane quarter
    s0 += __shfl_xor_sync(FULL, s0, 4);
    s1 += __shfl_xor_sync(FULL, s1, 4);
    s2 += __shfl_xor_sync(FULL, s2, 4);
    s3 += __shfl_xor_sync(FULL, s3, 4);
    s0 += __shfl_xor_sync(FULL, s0, 2);
    s1 += __shfl_xor_sync(FULL, s1, 2);
    s2 += __shfl_xor_sync(FULL, s2, 2);
    s3 += __shfl_xor_sync(FULL, s3, 2);
    s0 += __shfl_xor_sync(FULL, s0, 1);
    s1 += __shfl_xor_sync(FULL, s1, 1);
    s2 += __shfl_xor_sync(FULL, s2, 1);
    s3 += __shfl_xor_sync(FULL, s3, 1);

    // owner lane j (0..15): neighbor j = (j>>2)*4 + (j&3)? No: quarter q owns
    // neighbors t*4+q, so neighbor j is batch t=j>>2 from quarter q=j&3 (lane (j&3)*8).
    const int srcl = (lane & 3) << 3;
    const float c0 = __shfl_sync(FULL, s0, srcl);
    const float c1 = __shfl_sync(FULL, s1, srcl);
    const float c2 = __shfl_sync(FULL, s2, srcl);
    const float c3 = __shfl_sync(FULL, s3, srcl);
    const int t = lane >> 2;
    const float dist2 = (t == 0) ? c0 : (t == 1) ? c1 : (t == 2) ? c2 : c3;

    const float nd = (lane < KNB) ? -sqrtf(dist2 + 1e-8f) : -1e30f;

    // stable softmax: max over the 16 neighbor lanes (xor<16 never crosses halves)
    float m = nd;
    m = fmaxf(m, __shfl_xor_sync(FULL, m, 8));
    m = fmaxf(m, __shfl_xor_sync(FULL, m, 4));
    m = fmaxf(m, __shfl_xor_sync(FULL, m, 2));
    m = fmaxf(m, __shfl_xor_sync(FULL, m, 1));

    const float e = (lane < KNB) ? __expf((nd - m) * 10.0f) : 0.0f;   // 1/T = 10
    const bool ispos = (lane < KNB) && (nblab == lab);
    float pos = ispos ? e : 0.0f;
    float neg = e;
#pragma unroll
    for (int off = 8; off >= 1; off >>= 1) {
        pos += __shfl_xor_sync(FULL, pos, off);
        neg += __shfl_xor_sync(FULL, neg, off);
    }
    const int cnt = __popc(__ballot_sync(FULL, ispos) & 0xFFFFu);

    __shared__ float sn[8], sd[8];
    if (lane == 0) {
        const float pm = (active && cnt > 0 && cnt < KNB) ? 1.0f : 0.0f;
        const float loss = -__logf(pos / neg + 1e-8f);
        sn[wid] = loss * pm;
        sd[wid] = pm;
    }
    __syncthreads();
    if (threadIdx.x == 0) {
        float a = 0.0f, b = 0.0f;
#pragma unroll
        for (int i = 0; i < 8; i++) { a += sn[i]; b += sd[i]; }
        atomicAdd(&g_num, (double)a);
        atomicAdd(&g_den, (double)b);
    }
}

// Reads accumulators, writes the scalar loss, then RESETS them so the next graph
// replay starts from zero (deterministic: identical work and output every call).
__global__ void ch_finalize_kernel(float* __restrict__ out)
{
    if (threadIdx.x == 0) {
        double den = g_den;
        if (den < 1.0) den = 1.0;
        out[0] = (float)(g_num / den * 0.1);   // WEIGHT = 0.1
        g_num = 0.0;
        g_den = 0.0;
    }
}

extern "C" void kernel_launch(void* const* d_in, const int* in_sizes, int n_in,
                              void* d_out, int out_size) {
    const float* feat   = (const float*)d_in[0];
    const int*   labels = (const int*)d_in[1];
    const void*  nbr    = (const void*)d_in[2];
    float* out = (float*)d_out;
    (void)n_in; (void)out_size;

    const int n = in_sizes[1];        // N points
    const int blocks = (n + 7) / 8;   // warp per point, 8 warps/block

    ch_main_kernel<<<blocks, 256>>>(feat, labels, nbr, n);
    ch_finalize_kernel<<<1, 32>>>(out);
}

// round 14
// speedup vs baseline: 1.2081x; 1.0697x over previous
#include <cuda_runtime.h>

// ContrastHead: neighbor-contrastive loss.
//   N=200000 points, K=16 neighbors, C=32 features, T=0.1, weight=0.1, eps=1e-8
// Inputs: features f32 [N*C], labels i32 [N], neighbor_idx [N*K] (int32/int64 detect)
// Output: 1 float.
//
// R13: R11 split structure (best: 58.1us) with the gather loop restructured for
// MLP=4 — all 4 index shuffles, then 4 independent LDG.128s, then 4 parallel
// butterfly reductions. Profile showed main at ~80% issue AND ~80% L1tex with ~40%
// stall-idle slots; batching overlaps gather latency to close the issue gap.

#define KNB 16
#define CF  32

__device__ double g_num = 0.0;   // finalize re-zeroes after each read
__device__ double g_den = 0.0;

__global__ __launch_bounds__(256) void ch_main_kernel(
    const float* __restrict__ feat,
    const int*   __restrict__ labels,
    const void*  __restrict__ nbr,
    int n)
{
    const unsigned FULL = 0xffffffffu;
    const int lane = threadIdx.x & 31;
    const int wid  = threadIdx.x >> 5;
    const int wp   = (blockIdx.x * blockDim.x + threadIdx.x) >> 5;   // warp -> point
    const bool active = (wp < n);
    const int p = active ? wp : 0;
    const int s = lane & 7;    // float4 chunk within 128B row
    const int q = lane >> 3;   // quarter id 0..3

    // dtype detect: int64 -> odd 32-bit words of first 16 entries all zero.
    int probe = 1;
    if (lane < 16) probe = reinterpret_cast<const int*>(nbr)[2 * lane + 1];
    const bool is64 = ((__ballot_sync(FULL, probe == 0) & 0xFFFFu) == 0xFFFFu);

    const float4* __restrict__ feat4 = reinterpret_cast<const float4*>(feat);

    // issue idx + center loads up front
    int myidx = 0;
    if (lane < KNB) {
        if (is64)
            myidx = (int)reinterpret_cast<const long long*>(nbr)[(size_t)p * KNB + lane];
        else
            myidx = reinterpret_cast<const int*>(nbr)[(size_t)p * KNB + lane];
    }
    const float4 cf = feat4[(size_t)p * 8 + s];
    const int lab = labels[p];

    // batched gathers: quarter q handles neighbors t*4+q for t=0..3
    const int i0 = __shfl_sync(FULL, myidx,      q);
    const int i1 = __shfl_sync(FULL, myidx,  4 + q);
    const int i2 = __shfl_sync(FULL, myidx,  8 + q);
    const int i3 = __shfl_sync(FULL, myidx, 12 + q);
    const float4 nf0 = feat4[(size_t)i0 * 8 + s];
    const float4 nf1 = feat4[(size_t)i1 * 8 + s];
    const float4 nf2 = feat4[(size_t)i2 * 8 + s];
    const float4 nf3 = feat4[(size_t)i3 * 8 + s];
    const int nblab = labels[(lane < KNB) ? myidx : 0];

    float s0, s1, s2, s3;
    {
        float d0, d1, d2, d3;
        d0 = cf.x - nf0.x; d1 = cf.y - nf0.y; d2 = cf.z - nf0.z; d3 = cf.w - nf0.w;
        s0 = fmaf(d3, d3, fmaf(d2, d2, fmaf(d1, d1, d0 * d0)));
        d0 = cf.x - nf1.x; d1 = cf.y - nf1.y; d2 = cf.z - nf1.z; d3 = cf.w - nf1.w;
        s1 = fmaf(d3, d3, fmaf(d2, d2, fmaf(d1, d1, d0 * d0)));
        d0 = cf.x - nf2.x; d1 = cf.y - nf2.y; d2 = cf.z - nf2.z; d3 = cf.w - nf2.w;
        s2 = fmaf(d3, d3, fmaf(d2, d2, fmaf(d1, d1, d0 * d0)));
        d0 = cf.x - nf3.x; d1 = cf.y - nf3.y; d2 = cf.z - nf3.z; d3 = cf.w - nf3.w;
        s3 = fmaf(d3, d3, fmaf(d2, d2, fmaf(d1, d1, d0 * d0)));
    }
    // 4 independent butterfly chains within each 8-lane quarter
    s0 += __shfl_xor_sync(FULL, s0, 4);
    s1 += __shfl_xor_sync(FULL, s1, 4);
    s2 += __shfl_xor_sync(FULL, s2, 4);
    s3 += __shfl_xor_sync(FULL, s3, 4);
    s0 += __shfl_xor_sync(FULL, s0, 2);
    s1 += __shfl_xor_sync(FULL, s1, 2);
    s2 += __shfl_xor_sync(FULL, s2, 2);
    s3 += __shfl_xor_sync(FULL, s3, 2);
    s0 += __shfl_xor_sync(FULL, s0, 1);
    s1 += __shfl_xor_sync(FULL, s1, 1);
    s2 += __shfl_xor_sync(FULL, s2, 1);
    s3 += __shfl_xor_sync(FULL, s3, 1);

    // owner lane j (0..15): neighbor j = (j>>2)*4 + (j&3)? No: quarter q owns
    // neighbors t*4+q, so neighbor j is batch t=j>>2 from quarter q=j&3 (lane (j&3)*8).
    const int srcl = (lane & 3) << 3;
    const float c0 = __shfl_sync(FULL, s0, srcl);
    const float c1 = __shfl_sync(FULL, s1, srcl);
    const float c2 = __shfl_sync(FULL, s2, srcl);
    const float c3 = __shfl_sync(FULL, s3, srcl);
    const int t = lane >> 2;
    const float dist2 = (t == 0) ? c0 : (t == 1) ? c1 : (t == 2) ? c2 : c3;

    const float nd = (lane < KNB) ? -sqrtf(dist2 + 1e-8f) : -1e30f;

    // stable softmax: max over the 16 neighbor lanes (xor<16 never crosses halves)
    float m = nd;
    m = fmaxf(m, __shfl_xor_sync(FULL, m, 8));
    m = fmaxf(m, __shfl_xor_sync(FULL, m, 4));
    m = fmaxf(m, __shfl_xor_sync(FULL, m, 2));
    m = fmaxf(m, __shfl_xor_sync(FULL, m, 1));

    const float e = (lane < KNB) ? __expf((nd - m) * 10.0f) : 0.0f;   // 1/T = 10
    const bool ispos = (lane < KNB) && (nblab == lab);
    float pos = ispos ? e : 0.0f;
    float neg = e;
#pragma unroll
    for (int off = 8; off >= 1; off >>= 1) {
        pos += __shfl_xor_sync(FULL, pos, off);
        neg += __shfl_xor_sync(FULL, neg, off);
    }
    const int cnt = __popc(__ballot_sync(FULL, ispos) & 0xFFFFu);

    __shared__ float sn[8], sd[8];
    if (lane == 0) {
        const float pm = (active && cnt > 0 && cnt < KNB) ? 1.0f : 0.0f;
        const float loss = -__logf(pos / neg + 1e-8f);
        sn[wid] = loss * pm;
        sd[wid] = pm;
    }
    __syncthreads();
    if (threadIdx.x == 0) {
        float a = 0.0f, b = 0.0f;
#pragma unroll
        for (int i = 0; i < 8; i++) { a += sn[i]; b += sd[i]; }
        atomicAdd(&g_num, (double)a);
        atomicAdd(&g_den, (double)b);
    }
}

// Reads accumulators, writes the scalar loss, then RESETS them so the next graph
// replay starts from zero (deterministic: identical work and output every call).
__global__ void ch_finalize_kernel(float* __restrict__ out)
{
    if (threadIdx.x == 0) {
        double den = g_den;
        if (den < 1.0) den = 1.0;
        out[0] = (float)(g_num / den * 0.1);   // WEIGHT = 0.1
        g_num = 0.0;
        g_den = 0.0;
    }
}

extern "C" void kernel_launch(void* const* d_in, const int* in_sizes, int n_in,
                              void* d_out, int out_size) {
    const float* feat   = (const float*)d_in[0];
    const int*   labels = (const int*)d_in[1];
    const void*  nbr    = (const void*)d_in[2];
    float* out = (float*)d_out;
    (void)n_in; (void)out_size;

    const int n = in_sizes[1];        // N points
    const int blocks = (n + 7) / 8;   // warp per point, 8 warps/block

    ch_main_kernel<<<blocks, 256>>>(feat, labels, nbr, n);
    ch_finalize_kernel<<<1, 32>>>(out);
}